// round 1
// baseline (speedup 1.0000x reference)
#include <cuda_runtime.h>

#define IMG 256
#define NG 1024
#define PIX (1.0f/256.0f)
#define T_TH 1e-4f

// Sorted, precomputed per-Gaussian data (scratch: __device__ globals, no allocs)
__device__ float g_mx[NG], g_my[NG], g_i00[NG], g_ioff[NG], g_i11[NG];
__device__ float g_cr[NG], g_cg[NG], g_cb[NG], g_al[NG], g_rad2[NG];

// ---------------------------------------------------------------------------
// Kernel 1: sort by depth (bitonic on u64 keys = depth bits << 32 | index),
// precompute inverse covariance, colors, alpha, and conservative bounding
// radius^2 (quad > 40 outside => contribution < alpha*e^-20, negligible).
// ---------------------------------------------------------------------------
__global__ void __launch_bounds__(NG) prep_kernel(const float* __restrict__ mean,
                                                  const float* __restrict__ cov,
                                                  const float* __restrict__ color,
                                                  const float* __restrict__ alpha,
                                                  const float* __restrict__ depth) {
    __shared__ unsigned long long keys[NG];
    int t = threadIdx.x;
    // depth > 0, so float bit pattern is monotone as unsigned
    keys[t] = (((unsigned long long)__float_as_uint(depth[t])) << 32) | (unsigned)t;
    __syncthreads();

    for (int k = 2; k <= NG; k <<= 1) {
        for (int j = k >> 1; j > 0; j >>= 1) {
            int ixj = t ^ j;
            if (ixj > t) {
                unsigned long long a = keys[t], b = keys[ixj];
                bool doswap = ((t & k) == 0) ? (a > b) : (a < b);
                if (doswap) { keys[t] = b; keys[ixj] = a; }
            }
            __syncthreads();
        }
    }

    int src = (int)(keys[t] & 0xffffffffu);
    float a = cov[src*4+0], b = cov[src*4+1], c = cov[src*4+2], d = cov[src*4+3];
    float det = a*d - b*c;
    g_i00[t]  = d / det;
    g_i11[t]  = a / det;
    g_ioff[t] = -(b + c) / det;
    g_mx[t]   = mean[src*2+0];
    g_my[t]   = mean[src*2+1];
    g_cr[t]   = color[src*3+0];
    g_cg[t]   = color[src*3+1];
    g_cb[t]   = color[src*3+2];
    g_al[t]   = alpha[src];
    // max eigenvalue of (symmetrized) covariance -> conservative radius
    float bs      = 0.5f*(b + c);
    float half_tr = 0.5f*(a + d);
    float disc    = sqrtf(0.25f*(a - d)*(a - d) + bs*bs);
    g_rad2[t] = 40.0f * (half_tr + disc);
}

// ---------------------------------------------------------------------------
// Kernel 2: one 16x16 block per 16x16 pixel tile.
//   1) stage all Gaussian data into smem
//   2) order-preserving compaction of Gaussians intersecting this tile
//   3) per-pixel front-to-back composite with early termination
// ---------------------------------------------------------------------------
__global__ void __launch_bounds__(256) render_kernel(const float* __restrict__ bg,
                                                     const float* __restrict__ topleft,
                                                     float* __restrict__ out) {
    __shared__ float s_mx[NG], s_my[NG], s_i00[NG], s_ioff[NG], s_i11[NG];
    __shared__ float s_cr[NG], s_cg[NG], s_cb[NG], s_al[NG];
    __shared__ unsigned short s_list[NG];
    __shared__ int s_wsum[8];
    __shared__ int s_count;

    int tx = threadIdx.x, ty = threadIdx.y;
    int tid = ty*16 + tx;

    for (int i = tid; i < NG; i += 256) {
        s_mx[i]  = g_mx[i];  s_my[i]   = g_my[i];
        s_i00[i] = g_i00[i]; s_ioff[i] = g_ioff[i]; s_i11[i] = g_i11[i];
        s_cr[i]  = g_cr[i];  s_cg[i]   = g_cg[i];   s_cb[i]  = g_cb[i];
        s_al[i]  = g_al[i];
    }
    float tlx = topleft[0], tly = topleft[1];
    // bounds of pixel CENTERS in this tile
    float x0 = (blockIdx.x*16 + 0.5f)*PIX - tlx;
    float x1 = (blockIdx.x*16 + 15.5f)*PIX - tlx;
    float y0 = (blockIdx.y*16 + 0.5f)*PIX - tly;
    float y1 = (blockIdx.y*16 + 15.5f)*PIX - tly;
    if (tid == 0) s_count = 0;
    __syncthreads();

    int lane = tid & 31, warp = tid >> 5;
    for (int seg = 0; seg < 4; seg++) {
        int g = seg*256 + tid;
        float mx = s_mx[g], my = s_my[g];
        float cx = fminf(fmaxf(mx, x0), x1);
        float cy = fminf(fmaxf(my, y0), y1);
        float ddx = cx - mx, ddy = cy - my;
        bool keep = (ddx*ddx + ddy*ddy) <= g_rad2[g];
        unsigned bal = __ballot_sync(0xffffffffu, keep);
        if (lane == 0) s_wsum[warp] = __popc(bal);
        __syncthreads();
        int base = s_count;
        #pragma unroll
        for (int w = 0; w < 8; w++) if (w < warp) base += s_wsum[w];
        if (keep) s_list[base + __popc(bal & ((1u << lane) - 1u))] = (unsigned short)g;
        __syncthreads();
        if (tid == 0) {
            int tot = 0;
            #pragma unroll
            for (int w = 0; w < 8; w++) tot += s_wsum[w];
            s_count += tot;
        }
        __syncthreads();
    }
    int n = s_count;

    float px = (blockIdx.x*16 + tx + 0.5f)*PIX - tlx;
    float py = (blockIdx.y*16 + ty + 0.5f)*PIX - tly;
    float T = 1.0f, cr = 0.0f, cg = 0.0f, cb = 0.0f;

    for (int i = 0; i < n; i++) {
        int gi = s_list[i];
        float dx = px - s_mx[gi], dy = py - s_my[gi];
        float quad = s_i00[gi]*dx*dx + s_ioff[gi]*dx*dy + s_i11[gi]*dy*dy;
        float aeff = fminf(s_al[gi] * __expf(-0.5f*quad), 0.99f);
        float w = aeff * T;
        cr += w * s_cr[gi];
        cg += w * s_cg[gi];
        cb += w * s_cb[gi];
        T *= (1.0f - aeff);
        if (T <= T_TH) break;   // next Gaussian would be inactive (T_excl <= thresh)
    }

    int pi = ((blockIdx.y*16 + ty)*IMG + blockIdx.x*16 + tx)*3;
    out[pi+0] = cr + T*bg[pi+0];
    out[pi+1] = cg + T*bg[pi+1];
    out[pi+2] = cb + T*bg[pi+2];
}

extern "C" void kernel_launch(void* const* d_in, const int* in_sizes, int n_in,
                              void* d_out, int out_size) {
    const float* mean    = (const float*)d_in[0];
    const float* cov     = (const float*)d_in[1];
    const float* color   = (const float*)d_in[2];
    const float* alpha   = (const float*)d_in[3];
    const float* depth   = (const float*)d_in[4];
    const float* bg      = (const float*)d_in[5];
    const float* topleft = (const float*)d_in[6];

    prep_kernel<<<1, NG>>>(mean, cov, color, alpha, depth);
    dim3 grid(IMG/16, IMG/16), block(16, 16);
    render_kernel<<<grid, block>>>(bg, topleft, (float*)d_out);
}

// round 2
// speedup vs baseline: 1.3216x; 1.3216x over previous
#include <cuda_runtime.h>

#define IMG 256
#define NG 1024
#define PIX (1.0f/256.0f)
#define T_TH 1e-4f

// Sorted + packed per-Gaussian data (device scratch, no allocs)
__device__ float4 g_pa[NG];   // mx, my, c00, c01   (c = -0.5 * invCov)
__device__ float4 g_pb[NG];   // c11, cr, cg, cb
__device__ float  g_al[NG];
__device__ float  g_rad2[NG];

// ---------------------------------------------------------------------------
// Kernel 1: register-resident bitonic sort of (depthbits<<32 | idx) u64 keys.
// Intra-warp stages (j<32) via shfl_xor (no barriers); cross-warp stages via
// double-buffered smem (1 barrier each, 15 total). Then precompute packed data.
// ---------------------------------------------------------------------------
__global__ void __launch_bounds__(NG) prep_kernel(const float* __restrict__ mean,
                                                  const float* __restrict__ cov,
                                                  const float* __restrict__ color,
                                                  const float* __restrict__ alpha,
                                                  const float* __restrict__ depth) {
    __shared__ unsigned long long buf[2][NG];
    int t = threadIdx.x;
    // depth > 0 => float bits monotone as unsigned
    unsigned long long v = (((unsigned long long)__float_as_uint(depth[t])) << 32) | (unsigned)t;

    int ping = 0;
    for (int k = 2; k <= NG; k <<= 1) {
        bool up = ((t & k) == 0);
        for (int j = k >> 1; j > 0; j >>= 1) {
            unsigned long long w;
            if (j >= 32) {
                buf[ping][t] = v;
                __syncthreads();
                w = buf[ping][t ^ j];
                ping ^= 1;
            } else {
                w = __shfl_xor_sync(0xffffffffu, v, j);
            }
            bool lower = ((t & j) == 0);
            unsigned long long lo = v < w ? v : w;
            unsigned long long hi = v < w ? w : v;
            v = (lower == up) ? lo : hi;
        }
    }

    int src = (int)(v & 0xffffffffu);
    float a = cov[src*4+0], b = cov[src*4+1], c = cov[src*4+2], d = cov[src*4+3];
    float det = a*d - b*c;
    float i00  = d / det;
    float i11  = a / det;
    float ioff = -(b + c) / det;
    float mx = mean[src*2+0], my = mean[src*2+1];
    g_pa[t] = make_float4(mx, my, -0.5f*i00, -0.5f*ioff);
    g_pb[t] = make_float4(-0.5f*i11, color[src*3+0], color[src*3+1], color[src*3+2]);
    g_al[t] = alpha[src];
    // conservative radius^2: quad > 40 outside => contribution < alpha*e^-20
    float bs      = 0.5f*(b + c);
    float half_tr = 0.5f*(a + d);
    float disc    = sqrtf(0.25f*(a - d)*(a - d) + bs*bs);
    g_rad2[t] = 40.0f * (half_tr + disc);
}

// ---------------------------------------------------------------------------
// Kernel 2: 128 threads per 16x8 pixel tile (512 blocks).
//   1) cull straight from global, compact survivors into contiguous smem
//   2) per-pixel composite in chunks of 8 (ILP on LDS/exp; exact T-masking)
// ---------------------------------------------------------------------------
__global__ void __launch_bounds__(128) render_kernel(const float* __restrict__ bg,
                                                     const float* __restrict__ topleft,
                                                     float* __restrict__ out) {
    __shared__ float4 s_a[NG];
    __shared__ float4 s_b[NG];
    __shared__ float  s_al[NG];
    __shared__ int    s_wsum[4];
    __shared__ int    s_count;

    int tid  = threadIdx.x;
    int lane = tid & 31, warp = tid >> 5;

    float tlx = topleft[0], tly = topleft[1];
    // pixel-center bounds of this 16x8 tile
    float x0 = (blockIdx.x*16 + 0.5f)*PIX - tlx;
    float x1 = (blockIdx.x*16 + 15.5f)*PIX - tlx;
    float y0 = (blockIdx.y*8 + 0.5f)*PIX - tly;
    float y1 = (blockIdx.y*8 + 7.5f)*PIX - tly;
    if (tid == 0) s_count = 0;
    __syncthreads();

    #pragma unroll 1
    for (int seg = 0; seg < 8; seg++) {
        int g = seg*128 + tid;
        float4 pa = g_pa[g];
        float rad2 = g_rad2[g];
        float cx = fminf(fmaxf(pa.x, x0), x1) - pa.x;
        float cy = fminf(fmaxf(pa.y, y0), y1) - pa.y;
        bool keep = (cx*cx + cy*cy) <= rad2;
        unsigned bal = __ballot_sync(0xffffffffu, keep);
        if (lane == 0) s_wsum[warp] = __popc(bal);
        __syncthreads();
        int base = s_count;
        #pragma unroll
        for (int w = 0; w < 4; w++) if (w < warp) base += s_wsum[w];
        if (keep) {
            int pos = base + __popc(bal & ((1u << lane) - 1u));
            s_a[pos]  = pa;
            s_b[pos]  = g_pb[g];
            s_al[pos] = g_al[g];
        }
        __syncthreads();
        if (tid == 0) s_count += s_wsum[0] + s_wsum[1] + s_wsum[2] + s_wsum[3];
        __syncthreads();
    }
    int n = s_count;

    int tx = tid & 15, ty = tid >> 4;
    float px = (blockIdx.x*16 + tx + 0.5f)*PIX - tlx;
    float py = (blockIdx.y*8 + ty + 0.5f)*PIX - tly;
    float T = 1.0f, cr = 0.0f, cg = 0.0f, cb = 0.0f;

    for (int i = 0; i < n && T > T_TH; i += 8) {
        float a8[8], r8[8], g8[8], b8[8];
        #pragma unroll
        for (int u = 0; u < 8; u++) {
            int iu = i + u;
            int idx = iu < n ? iu : n - 1;
            float4 pa = s_a[idx];
            float4 pb = s_b[idx];
            float dx = px - pa.x, dy = py - pa.y;
            float q  = pa.z*dx*dx + pa.w*dx*dy + pb.x*dy*dy;
            float av = fminf(s_al[idx] * __expf(q), 0.99f);
            a8[u] = iu < n ? av : 0.0f;
            r8[u] = pb.y; g8[u] = pb.z; b8[u] = pb.w;
        }
        #pragma unroll
        for (int u = 0; u < 8; u++) {
            if (T > T_TH) {             // exact per-Gaussian active mask
                float w = a8[u] * T;
                cr = fmaf(w, r8[u], cr);
                cg = fmaf(w, g8[u], cg);
                cb = fmaf(w, b8[u], cb);
                T *= (1.0f - a8[u]);
            }
        }
    }

    int pi = ((blockIdx.y*8 + ty)*IMG + blockIdx.x*16 + tx)*3;
    out[pi+0] = cr + T*bg[pi+0];
    out[pi+1] = cg + T*bg[pi+1];
    out[pi+2] = cb + T*bg[pi+2];
}

extern "C" void kernel_launch(void* const* d_in, const int* in_sizes, int n_in,
                              void* d_out, int out_size) {
    const float* mean    = (const float*)d_in[0];
    const float* cov     = (const float*)d_in[1];
    const float* color   = (const float*)d_in[2];
    const float* alpha   = (const float*)d_in[3];
    const float* depth   = (const float*)d_in[4];
    const float* bg      = (const float*)d_in[5];
    const float* topleft = (const float*)d_in[6];

    prep_kernel<<<1, NG>>>(mean, cov, color, alpha, depth);
    dim3 grid(IMG/16, IMG/8), block(128);
    render_kernel<<<grid, block>>>(bg, topleft, (float*)d_out);
}

// round 3
// speedup vs baseline: 1.4138x; 1.0697x over previous
#include <cuda_runtime.h>

#define IMG 256
#define NG 1024
#define PIX (1.0f/256.0f)
#define T_TH 1e-4f

// Sorted + packed per-Gaussian data (device scratch, no allocs)
__device__ float4 g_cull[NG];  // mx, my, rad2, (pad)
__device__ float4 g_q[NG];     // c00, c01, c11, alpha   (c = -0.5 * invCov)
__device__ float4 g_c[NG];     // cr, cg, cb, (pad)

// ---------------------------------------------------------------------------
// Kernel 1: register-resident bitonic sort of (depthbits<<32 | idx) u64 keys.
// shfl_xor for intra-warp stages, double-buffered smem for cross-warp stages.
// ---------------------------------------------------------------------------
__global__ void __launch_bounds__(NG) prep_kernel(const float* __restrict__ mean,
                                                  const float* __restrict__ cov,
                                                  const float* __restrict__ color,
                                                  const float* __restrict__ alpha,
                                                  const float* __restrict__ depth) {
    __shared__ unsigned long long buf[2][NG];
    int t = threadIdx.x;
    // depth > 0 => float bits monotone as unsigned
    unsigned long long v = (((unsigned long long)__float_as_uint(depth[t])) << 32) | (unsigned)t;

    int ping = 0;
    for (int k = 2; k <= NG; k <<= 1) {
        bool up = ((t & k) == 0);
        for (int j = k >> 1; j > 0; j >>= 1) {
            unsigned long long w;
            if (j >= 32) {
                buf[ping][t] = v;
                __syncthreads();
                w = buf[ping][t ^ j];
                ping ^= 1;
            } else {
                w = __shfl_xor_sync(0xffffffffu, v, j);
            }
            bool lower = ((t & j) == 0);
            unsigned long long lo = v < w ? v : w;
            unsigned long long hi = v < w ? w : v;
            v = (lower == up) ? lo : hi;
        }
    }

    int src = (int)(v & 0xffffffffu);
    float a = cov[src*4+0], b = cov[src*4+1], c = cov[src*4+2], d = cov[src*4+3];
    float det = a*d - b*c;
    float i00  = d / det;
    float i11  = a / det;
    float ioff = -(b + c) / det;
    float mx = mean[src*2+0], my = mean[src*2+1];
    // conservative radius^2: quad > 40 outside => contribution < alpha*e^-20
    float bs      = 0.5f*(b + c);
    float half_tr = 0.5f*(a + d);
    float disc    = sqrtf(0.25f*(a - d)*(a - d) + bs*bs);
    g_cull[t] = make_float4(mx, my, 40.0f * (half_tr + disc), 0.0f);
    g_q[t]    = make_float4(-0.5f*i00, -0.5f*ioff, -0.5f*i11, alpha[src]);
    g_c[t]    = make_float4(color[src*3+0], color[src*3+1], color[src*3+2], 0.0f);
}

// ---------------------------------------------------------------------------
// Kernel 2: 128 threads per 16x8 pixel tile (512 blocks).
// Chunked: per 128-Gaussian sorted chunk -> cull+compact -> composite ->
// block-wide early exit once every pixel's transmittance is below threshold.
// ---------------------------------------------------------------------------
__global__ void __launch_bounds__(128) render_kernel(const float* __restrict__ bg,
                                                     const float* __restrict__ topleft,
                                                     float* __restrict__ out) {
    __shared__ float4 s_A[128];   // mx, my, c00, c01
    __shared__ float4 s_B[128];   // c11, al, cr, cg
    __shared__ float  s_cb[128];
    __shared__ int    s_wsum[4];

    int tid  = threadIdx.x;
    int lane = tid & 31, warp = tid >> 5;

    float tlx = topleft[0], tly = topleft[1];
    // pixel-center bounds of this 16x8 tile
    float x0 = (blockIdx.x*16 + 0.5f)*PIX - tlx;
    float x1 = (blockIdx.x*16 + 15.5f)*PIX - tlx;
    float y0 = (blockIdx.y*8 + 0.5f)*PIX - tly;
    float y1 = (blockIdx.y*8 + 7.5f)*PIX - tly;

    int tx = tid & 15, ty = tid >> 4;
    float px = (blockIdx.x*16 + tx + 0.5f)*PIX - tlx;
    float py = (blockIdx.y*8 + ty + 0.5f)*PIX - tly;

    int pi = ((blockIdx.y*8 + ty)*IMG + blockIdx.x*16 + tx)*3;
    float bgr = bg[pi+0], bgg = bg[pi+1], bgb = bg[pi+2];   // prefetch

    float T = 1.0f, cr = 0.0f, cg = 0.0f, cb = 0.0f;

    #pragma unroll 1
    for (int chunk = 0; chunk < 8; chunk++) {
        int g = chunk*128 + tid;
        float4 cu = g_cull[g];
        float cx = fminf(fmaxf(cu.x, x0), x1) - cu.x;
        float cy = fminf(fmaxf(cu.y, y0), y1) - cu.y;
        bool keep = (cx*cx + cy*cy) <= cu.z;
        unsigned bal = __ballot_sync(0xffffffffu, keep);
        if (lane == 0) s_wsum[warp] = __popc(bal);
        __syncthreads();
        int w0 = s_wsum[0], w1 = s_wsum[1], w2 = s_wsum[2], w3 = s_wsum[3];
        int n = w0 + w1 + w2 + w3;
        if (keep) {
            int base = (warp > 0 ? w0 : 0) + (warp > 1 ? w1 : 0) + (warp > 2 ? w2 : 0);
            int pos = base + __popc(bal & ((1u << lane) - 1u));
            float4 qv = g_q[g];
            float4 cv = g_c[g];
            s_A[pos]  = make_float4(cu.x, cu.y, qv.x, qv.y);
            s_B[pos]  = make_float4(qv.z, qv.w, cv.x, cv.y);
            s_cb[pos] = cv.z;
        }
        __syncthreads();

        if (T > T_TH) {
            for (int i = 0; i < n; i += 4) {
                float ax[4], rr[4], gg[4], bb[4];
                #pragma unroll
                for (int u = 0; u < 4; u++) {
                    int iu = i + u;
                    bool vld = iu < n;
                    int idx = vld ? iu : 0;
                    float4 A = s_A[idx];
                    float4 B = s_B[idx];
                    float dx = px - A.x, dy = py - A.y;
                    float qd = dx*(A.z*dx + A.w*dy) + B.x*dy*dy;
                    float av = fminf(B.y * __expf(qd), 0.99f);
                    ax[u] = vld ? av : 0.0f;
                    rr[u] = B.z; gg[u] = B.w; bb[u] = s_cb[idx];
                }
                float q0 = 1.0f-ax[0], q1 = 1.0f-ax[1], q2 = 1.0f-ax[2], q3 = 1.0f-ax[3];
                float p2 = q0*q1;
                float Tn = T * (p2*(q2*q3));
                if (Tn > T_TH) {
                    // fast path: all four steps provably active (T monotone dec.)
                    float t0 = T, t1 = T*q0, t2 = T*p2, t3 = t2*q2;
                    cr = fmaf(ax[0]*t0, rr[0], cr);
                    cg = fmaf(ax[0]*t0, gg[0], cg);
                    cb = fmaf(ax[0]*t0, bb[0], cb);
                    cr = fmaf(ax[1]*t1, rr[1], cr);
                    cg = fmaf(ax[1]*t1, gg[1], cg);
                    cb = fmaf(ax[1]*t1, bb[1], cb);
                    cr = fmaf(ax[2]*t2, rr[2], cr);
                    cg = fmaf(ax[2]*t2, gg[2], cg);
                    cb = fmaf(ax[2]*t2, bb[2], cb);
                    cr = fmaf(ax[3]*t3, rr[3], cr);
                    cg = fmaf(ax[3]*t3, gg[3], cg);
                    cb = fmaf(ax[3]*t3, bb[3], cb);
                    T = Tn;
                } else {
                    // crossing chunk: exact masked sequential (runs at most once)
                    #pragma unroll
                    for (int u = 0; u < 4; u++) {
                        if (T > T_TH) {
                            float w = ax[u] * T;
                            cr = fmaf(w, rr[u], cr);
                            cg = fmaf(w, gg[u], cg);
                            cb = fmaf(w, bb[u], cb);
                            T *= (1.0f - ax[u]);
                        }
                    }
                }
                if (T <= T_TH) break;
            }
        }
        if (__syncthreads_and(T <= T_TH)) break;   // whole tile saturated
    }

    out[pi+0] = cr + T*bgr;
    out[pi+1] = cg + T*bgg;
    out[pi+2] = cb + T*bgb;
}

extern "C" void kernel_launch(void* const* d_in, const int* in_sizes, int n_in,
                              void* d_out, int out_size) {
    const float* mean    = (const float*)d_in[0];
    const float* cov     = (const float*)d_in[1];
    const float* color   = (const float*)d_in[2];
    const float* alpha   = (const float*)d_in[3];
    const float* depth   = (const float*)d_in[4];
    const float* bg      = (const float*)d_in[5];
    const float* topleft = (const float*)d_in[6];

    prep_kernel<<<1, NG>>>(mean, cov, color, alpha, depth);
    dim3 grid(IMG/16, IMG/8), block(128);
    render_kernel<<<grid, block>>>(bg, topleft, (float*)d_out);
}